// round 1
// baseline (speedup 1.0000x reference)
#include <cuda_runtime.h>
#include <cstdint>

#define TH 1.0f
#define EPS_BN 1e-5f

// 256x256 distance matrix scratch (no allocations allowed -> device global)
__device__ float g_dm[256 * 256];

// ---------------------------------------------------------------------------
// Kernel 1: compute dm[n,m] = 0.5*(exp(s(n,m)) + exp(s(m,n)))
// s(n,m) = K + sum_o a[o]*relu(w1[o,0]*d0 + w1[o,1]*d1 + b1[o]),
//   d = x[:,n]-x[:,m],  a[o] = w2[o]*gamma[o]*rsqrt(var[o]+eps),
//   K = b2 + sum_o w2[o]*(beta[o] - mean[o]*scale[o])
// ---------------------------------------------------------------------------
__global__ void dm_kernel(const float* __restrict__ v,
                          const float* __restrict__ w1,
                          const float* __restrict__ b1,
                          const float* __restrict__ bn_gamma,
                          const float* __restrict__ bn_beta,
                          const float* __restrict__ bn_mean,
                          const float* __restrict__ bn_var,
                          const float* __restrict__ w2,
                          const float* __restrict__ b2) {
    __shared__ float sa[32], sw0[32], sw1[32], sb[32];
    __shared__ float sK;
    int tid = threadIdx.x;
    if (tid < 32) {
        float scale = bn_gamma[tid] * rsqrtf(bn_var[tid] + EPS_BN);
        float w2o = w2[tid];
        sa[tid]  = w2o * scale;
        sw0[tid] = w1[tid * 2 + 0];
        sw1[tid] = w1[tid * 2 + 1];
        sb[tid]  = b1[tid];
        float kpart = w2o * (bn_beta[tid] - bn_mean[tid] * scale);
        #pragma unroll
        for (int off = 16; off > 0; off >>= 1)
            kpart += __shfl_down_sync(0xffffffffu, kpart, off);
        if (tid == 0) sK = kpart + b2[0];
    }
    __syncthreads();

    int n = blockIdx.x;
    int m = tid;
    // x[c][i] = v_rel[0, c, 127, i], c in {0,1}; layout (1,256,128,256)
    const int base = 127 * 256;
    float x0n = v[base + n];
    float x1n = v[32768 + base + n];
    float x0m = v[base + m];
    float x1m = v[32768 + base + m];
    float d0 = x0n - x0m;
    float d1 = x1n - x1m;

    float sp = sK, sn = sK;
    #pragma unroll
    for (int o = 0; o < 32; o++) {
        float lin = sw0[o] * d0 + sw1[o] * d1;
        sp += sa[o] * fmaxf(lin + sb[o], 0.0f);
        sn += sa[o] * fmaxf(sb[o] - lin, 0.0f);
    }
    g_dm[n * 256 + m] = 0.5f * (expf(sp) + expf(sn));
}

// ---------------------------------------------------------------------------
// Kernel 2: exact replica of the reference lax.scan label merge, row-parallel.
//
// Reference semantics per ok edge (r,c), c<r, processed in row-major order:
//   labels[labels == labels[r]] = labels[c]
// Final labels == roots under ordered union "comp(r) absorbed into comp(c)".
// Per row r, the net effect: all components {comp(c): ok(r,c)} U {comp(r)}
// merge, and the merged component's id becomes comp(c*) where c* is the
// largest c whose component's FIRST occurrence in the ascending scan is c
// (and differs from comp(r)). Component id == its label (labels never
// mutate per-id; absorption just re-points members at the absorber's id).
// Then group_indices = rank of label among present labels (ascending).
// ---------------------------------------------------------------------------
__global__ void group_kernel(float* __restrict__ out_gi) {
    __shared__ int comp[256];
    __shared__ int firstidx[256];
    __shared__ int marked[256];
    __shared__ int cstar;
    __shared__ int newcomp;
    int tid = threadIdx.x;
    comp[tid] = tid;
    __syncthreads();

    for (int r = 1; r < 256; r++) {
        firstidx[tid] = 0x7fffffff;
        marked[tid] = 0;
        if (tid == 0) cstar = -1;
        __syncthreads();

        int myc = comp[tid];
        int rcomp = comp[r];
        bool okc = (tid < r) && (g_dm[r * 256 + tid] <= TH);
        if (okc) {
            atomicMin(&firstidx[myc], tid);
            marked[myc] = 1;
        }
        if (tid == r) marked[myc] = 1;   // mark comp(r)
        __syncthreads();

        if (okc && myc != rcomp && firstidx[myc] == tid)
            atomicMax(&cstar, tid);
        __syncthreads();

        int cs = cstar;
        if (cs >= 0) {
            if (tid == cs) newcomp = myc;
        }
        __syncthreads();
        if (cs >= 0 && marked[myc]) comp[tid] = newcomp;

        // early exit once a single component remains: every further edge is a
        // no-op under the reference semantics (labels[r]==labels[c]).
        if (__syncthreads_and(comp[tid] == comp[0])) break;
    }
    __syncthreads();

    // ranks: present labels, cumsum, rank lookup
    __shared__ int pres[256];
    pres[tid] = 0;
    __syncthreads();
    pres[comp[tid]] = 1;
    __syncthreads();
    // Hillis-Steele inclusive scan
    for (int off = 1; off < 256; off <<= 1) {
        int t = (tid >= off) ? pres[tid - off] : 0;
        __syncthreads();
        pres[tid] += t;
        __syncthreads();
    }
    int rank = pres[comp[tid]] - 1;
    out_gi[tid] = (float)rank;
}

// ---------------------------------------------------------------------------
// Kernel 3: v_grouped = v_rel (exact algebra of stop_gradient trick) and
// dist_mat_full = broadcast of dm over T=128. Pure bandwidth, float4 moves.
// ---------------------------------------------------------------------------
__global__ void out_kernel(const float* __restrict__ v, float* __restrict__ out) {
    const float4* __restrict__ v4  = (const float4*)v;
    const float4* __restrict__ dm4 = (const float4*)g_dm;
    float4* __restrict__ ov = (float4*)out;                 // 2097152 float4
    float4* __restrict__ od = (float4*)(out + 8388864);     // 2097152 float4
    int stride = gridDim.x * blockDim.x;
    int i0 = blockIdx.x * blockDim.x + threadIdx.x;
    for (int i = i0; i < 2097152; i += stride) ov[i] = v4[i];
    for (int i = i0; i < 2097152; i += stride) od[i] = dm4[i & 16383];
}

extern "C" void kernel_launch(void* const* d_in, const int* in_sizes, int n_in,
                              void* d_out, int out_size) {
    const float* v_rel    = (const float*)d_in[0];
    const float* w1       = (const float*)d_in[1];
    const float* b1       = (const float*)d_in[2];
    const float* bn_gamma = (const float*)d_in[3];
    const float* bn_beta  = (const float*)d_in[4];
    const float* bn_mean  = (const float*)d_in[5];
    const float* bn_var   = (const float*)d_in[6];
    const float* w2       = (const float*)d_in[7];
    const float* b2       = (const float*)d_in[8];
    float* out = (float*)d_out;

    dm_kernel<<<256, 256>>>(v_rel, w1, b1, bn_gamma, bn_beta, bn_mean, bn_var, w2, b2);
    group_kernel<<<1, 256>>>(out + 8388608);
    out_kernel<<<2048, 256>>>(v_rel, out);
}

// round 3
// speedup vs baseline: 6.9108x; 6.9108x over previous
#include <cuda_runtime.h>
#include <cstdint>

#define TH 1.0f
#define EPS_BN 1e-5f

// scratch (no allocations allowed -> device globals)
__device__ float g_dm[256 * 256];
__device__ int   g_rowok[256];

// ---------------------------------------------------------------------------
// Kernel 1: block n computes dm row n, writes it to g_dm, broadcasts it into
// dist_mat_full (128 T-copies), and records rowok[n] = (exists c<n ok).
// dm[n,m] = 0.5*(exp(s(n,m)) + exp(s(m,n)))
// s(n,m) = K + sum_o a[o]*relu(w1[o,0]*d0 + w1[o,1]*d1 + b1[o])
// ---------------------------------------------------------------------------
__global__ void dm_kernel(const float* __restrict__ v,
                          const float* __restrict__ w1,
                          const float* __restrict__ b1,
                          const float* __restrict__ bn_gamma,
                          const float* __restrict__ bn_beta,
                          const float* __restrict__ bn_mean,
                          const float* __restrict__ bn_var,
                          const float* __restrict__ w2,
                          const float* __restrict__ b2,
                          float* __restrict__ out_dist) {
    __shared__ __align__(16) float srow[256];   // float4-read below: must be 16B aligned
    __shared__ float sa[32], sw0[32], sw1[32], sb[32];
    __shared__ float sK;
    int tid = threadIdx.x;
    if (tid < 32) {
        float scale = bn_gamma[tid] * rsqrtf(bn_var[tid] + EPS_BN);
        float w2o = w2[tid];
        sa[tid]  = w2o * scale;
        sw0[tid] = w1[tid * 2 + 0];
        sw1[tid] = w1[tid * 2 + 1];
        sb[tid]  = b1[tid];
        float kpart = w2o * (bn_beta[tid] - bn_mean[tid] * scale);
        #pragma unroll
        for (int off = 16; off > 0; off >>= 1)
            kpart += __shfl_down_sync(0xffffffffu, kpart, off);
        if (tid == 0) sK = kpart + b2[0];
    }
    __syncthreads();

    int n = blockIdx.x;
    int m = tid;
    // x[c][i] = v_rel[0, c, 127, i], layout (1,256,128,256)
    const int base = 127 * 256;
    float d0 = v[base + n] - v[base + m];
    float d1 = v[32768 + base + n] - v[32768 + base + m];

    float sp = sK, sn = sK;
    #pragma unroll
    for (int o = 0; o < 32; o++) {
        float lin = sw0[o] * d0 + sw1[o] * d1;
        sp += sa[o] * fmaxf(lin + sb[o], 0.0f);
        sn += sa[o] * fmaxf(sb[o] - lin, 0.0f);
    }
    float val = 0.5f * (expf(sp) + expf(sn));
    g_dm[n * 256 + m] = val;
    srow[m] = val;

    int anyok = __syncthreads_or((m < n) && (val <= TH));
    if (tid == 0) g_rowok[n] = anyok;

    // broadcast row n into dist_mat_full: out_dist[t*65536 + n*256 + ...]
    const float4* __restrict__ src = (const float4*)srow;
    float4* __restrict__ dst = (float4*)out_dist;
    #pragma unroll 4
    for (int idx = tid; idx < 128 * 64; idx += 256) {
        int t = idx >> 6;
        int q = idx & 63;
        dst[t * 16384 + n * 64 + q] = src[q];
    }
}

// ---------------------------------------------------------------------------
// Kernel 2: group indices.
// FAST PATH: if every row r in [1,255] has >=1 ok edge to some c<r, the
// ordered-scan union yields a single component labeled 0 -> all ranks 0.
// SLOW PATH: exact row-parallel replica of the reference lax.scan (proven R1).
// ---------------------------------------------------------------------------
__global__ void group_kernel(float* __restrict__ out_gi) {
    int tid = threadIdx.x;
    int rowok = g_rowok[tid];
    if (__syncthreads_and(tid == 0 || rowok)) {
        out_gi[tid] = 0.0f;
        return;
    }

    // ---- exact fallback (rarely taken) ----
    __shared__ int comp[256];
    __shared__ int firstidx[256];
    __shared__ int marked[256];
    __shared__ int cstar;
    __shared__ int newcomp;
    comp[tid] = tid;
    __syncthreads();

    for (int r = 1; r < 256; r++) {
        firstidx[tid] = 0x7fffffff;
        marked[tid] = 0;
        if (tid == 0) cstar = -1;
        __syncthreads();

        int myc = comp[tid];
        int rcomp = comp[r];
        bool okc = (tid < r) && (g_dm[r * 256 + tid] <= TH);
        if (okc) {
            atomicMin(&firstidx[myc], tid);
            marked[myc] = 1;
        }
        if (tid == r) marked[myc] = 1;
        __syncthreads();

        if (okc && myc != rcomp && firstidx[myc] == tid)
            atomicMax(&cstar, tid);
        __syncthreads();

        int cs = cstar;
        if (cs >= 0 && tid == cs) newcomp = myc;
        __syncthreads();
        if (cs >= 0 && marked[myc]) comp[tid] = newcomp;
        __syncthreads();
    }

    __shared__ int pres[256];
    pres[tid] = 0;
    __syncthreads();
    pres[comp[tid]] = 1;
    __syncthreads();
    for (int off = 1; off < 256; off <<= 1) {
        int t = (tid >= off) ? pres[tid - off] : 0;
        __syncthreads();
        pres[tid] += t;
        __syncthreads();
    }
    out_gi[tid] = (float)(pres[comp[tid]] - 1);
}

// ---------------------------------------------------------------------------
// Kernel 3: v_grouped = v_rel (stop_gradient identity). Pure 67MB move.
// ---------------------------------------------------------------------------
__global__ void copy_kernel(const float* __restrict__ v, float* __restrict__ out) {
    const float4* __restrict__ v4 = (const float4*)v;
    float4* __restrict__ ov = (float4*)out;   // 2097152 float4
    int stride = gridDim.x * blockDim.x;
    for (int i = blockIdx.x * blockDim.x + threadIdx.x; i < 2097152; i += stride)
        ov[i] = v4[i];
}

extern "C" void kernel_launch(void* const* d_in, const int* in_sizes, int n_in,
                              void* d_out, int out_size) {
    const float* v_rel    = (const float*)d_in[0];
    const float* w1       = (const float*)d_in[1];
    const float* b1       = (const float*)d_in[2];
    const float* bn_gamma = (const float*)d_in[3];
    const float* bn_beta  = (const float*)d_in[4];
    const float* bn_mean  = (const float*)d_in[5];
    const float* bn_var   = (const float*)d_in[6];
    const float* w2       = (const float*)d_in[7];
    const float* b2       = (const float*)d_in[8];
    float* out = (float*)d_out;

    dm_kernel<<<256, 256>>>(v_rel, w1, b1, bn_gamma, bn_beta, bn_mean, bn_var,
                            w2, b2, out + 8388864);
    group_kernel<<<1, 256>>>(out + 8388608);
    copy_kernel<<<2048, 256>>>(v_rel, out);
}

// round 4
// speedup vs baseline: 7.4375x; 1.0762x over previous
#include <cuda_runtime.h>
#include <cstdint>

#define TH 1.0f
#define EPS_BN 1e-5f

// scratch (no allocations allowed -> device globals)
__device__ float g_dm[256 * 256];
__device__ int   g_rowok[256];

// ---------------------------------------------------------------------------
// Fused kernel, 3072 blocks x 256 threads:
//  blocks 0..1023 : dm row n = b>>2, slice s = b&3. Compute the MLP row
//    (thread m -> dm[n][m]) into shared, then write 32 t-copies of the row
//    into dist_mat_full (t in [s*32, s*32+32)). Slice 0 also stores g_dm row
//    and rowok[n] (any m<n with val<=TH).
//  blocks 1024..3071 : grid-slab float4 copy v_rel -> v_grouped
//    (stop_gradient(v - v_soft) + v_soft == v exactly).
// Every block carries ~32KB of DRAM traffic -> balanced, bandwidth-bound.
// ---------------------------------------------------------------------------
__global__ void fused_kernel(const float* __restrict__ v,
                             const float* __restrict__ w1,
                             const float* __restrict__ b1,
                             const float* __restrict__ bn_gamma,
                             const float* __restrict__ bn_beta,
                             const float* __restrict__ bn_mean,
                             const float* __restrict__ bn_var,
                             const float* __restrict__ w2,
                             const float* __restrict__ b2,
                             float* __restrict__ out) {
    int b = blockIdx.x;
    int tid = threadIdx.x;

    if (b >= 1024) {
        // ---- copy part: v_grouped = v_rel (2M float4 over 2048 blocks) ----
        const float4* __restrict__ v4 = (const float4*)v;
        float4* __restrict__ ov = (float4*)out;
        int i0 = (b - 1024) * 1024 + tid;
        #pragma unroll
        for (int k = 0; k < 4; k++)
            ov[i0 + k * 256] = v4[i0 + k * 256];
        return;
    }

    // ---- dm + dist broadcast part ----
    __shared__ __align__(16) float srow[256];
    __shared__ float sa[32], sw0[32], sw1[32], sb[32];
    __shared__ float sK;
    if (tid < 32) {
        float scale = bn_gamma[tid] * rsqrtf(bn_var[tid] + EPS_BN);
        float w2o = w2[tid];
        sa[tid]  = w2o * scale;
        sw0[tid] = w1[tid * 2 + 0];
        sw1[tid] = w1[tid * 2 + 1];
        sb[tid]  = b1[tid];
        float kpart = w2o * (bn_beta[tid] - bn_mean[tid] * scale);
        #pragma unroll
        for (int off = 16; off > 0; off >>= 1)
            kpart += __shfl_down_sync(0xffffffffu, kpart, off);
        if (tid == 0) sK = kpart + b2[0];
    }
    __syncthreads();

    int n = b >> 2;
    int s = b & 3;
    int m = tid;
    // x[c][i] = v_rel[0, c, 127, i], layout (1,256,128,256)
    const int base = 127 * 256;
    float d0 = v[base + n] - v[base + m];
    float d1 = v[32768 + base + n] - v[32768 + base + m];

    float sp = sK, sn = sK;
    #pragma unroll
    for (int o = 0; o < 32; o++) {
        float lin = sw0[o] * d0 + sw1[o] * d1;
        sp += sa[o] * fmaxf(lin + sb[o], 0.0f);
        sn += sa[o] * fmaxf(sb[o] - lin, 0.0f);
    }
    float val = 0.5f * (expf(sp) + expf(sn));
    srow[m] = val;

    int anyok = __syncthreads_or((m < n) && (val <= TH));   // doubles as barrier
    if (s == 0) {
        g_dm[n * 256 + m] = val;
        if (tid == 0) g_rowok[n] = anyok;
    }

    // dist_mat_full broadcast: t-copies [s*32, s*32+32), float4 granularity.
    const float4* __restrict__ src = (const float4*)srow;
    float4* __restrict__ dst = (float4*)(out + 8388864);
    int tbase = s * 32;
    #pragma unroll
    for (int k = 0; k < 8; k++) {
        int idx = tid + k * 256;        // 0..2047
        int t = tbase + (idx >> 6);
        int q = idx & 63;
        dst[t * 16384 + n * 64 + q] = src[q];
    }
}

// ---------------------------------------------------------------------------
// Kernel 2: group indices.
// FAST PATH: if every row r in [1,255] has >=1 ok edge to some c<r, the
// ordered-scan union yields a single component labeled 0 -> all ranks 0.
// SLOW PATH: exact row-parallel replica of the reference lax.scan.
// ---------------------------------------------------------------------------
__global__ void group_kernel(float* __restrict__ out_gi) {
    int tid = threadIdx.x;
    int rowok = g_rowok[tid];
    if (__syncthreads_and(tid == 0 || rowok)) {
        out_gi[tid] = 0.0f;
        return;
    }

    // ---- exact fallback (rarely taken) ----
    __shared__ int comp[256];
    __shared__ int firstidx[256];
    __shared__ int marked[256];
    __shared__ int cstar;
    __shared__ int newcomp;
    comp[tid] = tid;
    __syncthreads();

    for (int r = 1; r < 256; r++) {
        firstidx[tid] = 0x7fffffff;
        marked[tid] = 0;
        if (tid == 0) cstar = -1;
        __syncthreads();

        int myc = comp[tid];
        int rcomp = comp[r];
        bool okc = (tid < r) && (g_dm[r * 256 + tid] <= TH);
        if (okc) {
            atomicMin(&firstidx[myc], tid);
            marked[myc] = 1;
        }
        if (tid == r) marked[myc] = 1;
        __syncthreads();

        if (okc && myc != rcomp && firstidx[myc] == tid)
            atomicMax(&cstar, tid);
        __syncthreads();

        int cs = cstar;
        if (cs >= 0 && tid == cs) newcomp = myc;
        __syncthreads();
        if (cs >= 0 && marked[myc]) comp[tid] = newcomp;
        __syncthreads();
    }

    __shared__ int pres[256];
    pres[tid] = 0;
    __syncthreads();
    pres[comp[tid]] = 1;
    __syncthreads();
    for (int off = 1; off < 256; off <<= 1) {
        int t = (tid >= off) ? pres[tid - off] : 0;
        __syncthreads();
        pres[tid] += t;
        __syncthreads();
    }
    out_gi[tid] = (float)(pres[comp[tid]] - 1);
}

extern "C" void kernel_launch(void* const* d_in, const int* in_sizes, int n_in,
                              void* d_out, int out_size) {
    const float* v_rel    = (const float*)d_in[0];
    const float* w1       = (const float*)d_in[1];
    const float* b1       = (const float*)d_in[2];
    const float* bn_gamma = (const float*)d_in[3];
    const float* bn_beta  = (const float*)d_in[4];
    const float* bn_mean  = (const float*)d_in[5];
    const float* bn_var   = (const float*)d_in[6];
    const float* w2       = (const float*)d_in[7];
    const float* b2       = (const float*)d_in[8];
    float* out = (float*)d_out;

    fused_kernel<<<3072, 256>>>(v_rel, w1, b1, bn_gamma, bn_beta, bn_mean,
                                bn_var, w2, b2, out);
    group_kernel<<<1, 256>>>(out + 8388608);
}

// round 5
// speedup vs baseline: 9.2581x; 1.2448x over previous
#include <cuda_runtime.h>
#include <cstdint>

#define TH 1.0f
#define EPS_BN 1e-5f

// scratch (no allocations allowed -> device globals)
__device__ float g_dm[256 * 256];
__device__ int   g_rowok[256];
__device__ int   g_done = 0;   // reset to 0 by the last block each run (replay-safe)

// ---------------------------------------------------------------------------
// Single fused kernel, 3072 blocks x 256 threads:
//  blocks 0..1023 : dm row n = b>>2, slice s = b&3. Compute the MLP row
//    (thread m -> dm[n][m]) into shared, write 32 t-copies into
//    dist_mat_full. Slice 0 stores g_dm row + rowok[n], then joins a
//    done-counter; the LAST slice-0 block computes group_indices in-kernel
//    (fast path all-zeros; exact lax.scan replica fallback) and resets the
//    counter.
//  blocks 1024..3071 : float4 slab copy v_rel -> v_grouped
//    (stop_gradient(v - v_soft) + v_soft == v exactly).
// ---------------------------------------------------------------------------
__global__ void fused_kernel(const float* __restrict__ v,
                             const float* __restrict__ w1,
                             const float* __restrict__ b1,
                             const float* __restrict__ bn_gamma,
                             const float* __restrict__ bn_beta,
                             const float* __restrict__ bn_mean,
                             const float* __restrict__ bn_var,
                             const float* __restrict__ w2,
                             const float* __restrict__ b2,
                             float* __restrict__ out) {
    int b = blockIdx.x;
    int tid = threadIdx.x;

    if (b >= 1024) {
        // ---- copy part: v_grouped = v_rel (2M float4 over 2048 blocks) ----
        const float4* __restrict__ v4 = (const float4*)v;
        float4* __restrict__ ov = (float4*)out;
        int i0 = (b - 1024) * 1024 + tid;
        #pragma unroll
        for (int k = 0; k < 4; k++) {
            float4 val = v4[i0 + k * 256];
            __stcs(&ov[i0 + k * 256], val);
        }
        return;
    }

    // ---- dm + dist broadcast part ----
    __shared__ __align__(16) float srow[256];
    __shared__ float sa[32], sw0[32], sw1[32], sb[32];
    __shared__ float sK;
    __shared__ int s_islast;
    if (tid < 32) {
        float scale = bn_gamma[tid] * rsqrtf(bn_var[tid] + EPS_BN);
        float w2o = w2[tid];
        sa[tid]  = w2o * scale;
        sw0[tid] = w1[tid * 2 + 0];
        sw1[tid] = w1[tid * 2 + 1];
        sb[tid]  = b1[tid];
        float kpart = w2o * (bn_beta[tid] - bn_mean[tid] * scale);
        #pragma unroll
        for (int off = 16; off > 0; off >>= 1)
            kpart += __shfl_down_sync(0xffffffffu, kpart, off);
        if (tid == 0) sK = kpart + b2[0];
    }
    __syncthreads();

    int n = b >> 2;
    int s = b & 3;
    int m = tid;
    // x[c][i] = v_rel[0, c, 127, i], layout (1,256,128,256)
    const int base = 127 * 256;
    float d0 = v[base + n] - v[base + m];
    float d1 = v[32768 + base + n] - v[32768 + base + m];

    float sp = sK, sn = sK;
    #pragma unroll
    for (int o = 0; o < 32; o++) {
        float lin = sw0[o] * d0 + sw1[o] * d1;
        sp += sa[o] * fmaxf(lin + sb[o], 0.0f);
        sn += sa[o] * fmaxf(sb[o] - lin, 0.0f);
    }
    float val = 0.5f * (expf(sp) + expf(sn));
    srow[m] = val;

    int anyok = __syncthreads_or((m < n) && (val <= TH));   // doubles as barrier
    if (s == 0) {
        g_dm[n * 256 + m] = val;
        if (tid == 0) g_rowok[n] = anyok;
    }

    // dist_mat_full broadcast: t-copies [s*32, s*32+32), float4 granularity.
    const float4* __restrict__ src = (const float4*)srow;
    float4* __restrict__ dst = (float4*)(out + 8388864);
    int tbase = s * 32;
    #pragma unroll
    for (int k = 0; k < 8; k++) {
        int idx = tid + k * 256;        // 0..2047
        int t = tbase + (idx >> 6);
        int q = idx & 63;
        __stcs(&dst[t * 16384 + n * 64 + q], src[q]);
    }

    if (s != 0) return;

    // ---- done-counter handshake: last slice-0 block computes groups ----
    if (tid == 0) {
        __threadfence();                       // commit g_dm row + rowok
        int old = atomicAdd(&g_done, 1);
        s_islast = (old == 255);
    }
    __syncthreads();
    if (!s_islast) return;
    __threadfence();                           // see all rows' writes

    float* __restrict__ out_gi = out + 8388608;
    int rowok = g_rowok[tid];
    bool fast = __syncthreads_and(tid == 0 || rowok);
    if (fast) {
        // every row r>=1 merges into the component labeled 0 -> all ranks 0
        out_gi[tid] = 0.0f;
    } else {
        // ---- exact fallback: row-parallel replica of reference lax.scan ----
        __shared__ int comp[256];
        __shared__ int firstidx[256];
        __shared__ int marked[256];
        __shared__ int cstar;
        __shared__ int newcomp;
        comp[tid] = tid;
        __syncthreads();

        for (int r = 1; r < 256; r++) {
            firstidx[tid] = 0x7fffffff;
            marked[tid] = 0;
            if (tid == 0) cstar = -1;
            __syncthreads();

            int myc = comp[tid];
            int rcomp = comp[r];
            bool okc = (tid < r) && (g_dm[r * 256 + tid] <= TH);
            if (okc) {
                atomicMin(&firstidx[myc], tid);
                marked[myc] = 1;
            }
            if (tid == r) marked[myc] = 1;
            __syncthreads();

            if (okc && myc != rcomp && firstidx[myc] == tid)
                atomicMax(&cstar, tid);
            __syncthreads();

            int cs = cstar;
            if (cs >= 0 && tid == cs) newcomp = myc;
            __syncthreads();
            if (cs >= 0 && marked[myc]) comp[tid] = newcomp;
            __syncthreads();
        }

        __shared__ int pres[256];
        pres[tid] = 0;
        __syncthreads();
        pres[comp[tid]] = 1;
        __syncthreads();
        for (int off = 1; off < 256; off <<= 1) {
            int t = (tid >= off) ? pres[tid - off] : 0;
            __syncthreads();
            pres[tid] += t;
            __syncthreads();
        }
        out_gi[tid] = (float)(pres[comp[tid]] - 1);
    }
    __syncthreads();
    if (tid == 0) g_done = 0;                  // reset for next graph replay
}

extern "C" void kernel_launch(void* const* d_in, const int* in_sizes, int n_in,
                              void* d_out, int out_size) {
    const float* v_rel    = (const float*)d_in[0];
    const float* w1       = (const float*)d_in[1];
    const float* b1       = (const float*)d_in[2];
    const float* bn_gamma = (const float*)d_in[3];
    const float* bn_beta  = (const float*)d_in[4];
    const float* bn_mean  = (const float*)d_in[5];
    const float* bn_var   = (const float*)d_in[6];
    const float* w2       = (const float*)d_in[7];
    const float* b2       = (const float*)d_in[8];
    float* out = (float*)d_out;

    fused_kernel<<<3072, 256>>>(v_rel, w1, b1, bn_gamma, bn_beta, bn_mean,
                                bn_var, w2, b2, out);
}